// round 11
// baseline (speedup 1.0000x reference)
#include <cuda_runtime.h>
#include <cuda_fp16.h>
#include <math.h>
#include <stdint.h>

// ---------------- problem constants ----------------
#define NN 20000
#define EE 200000
#define HSZ (1u<<19)
#define HMASK (HSZ-1u)
#define NEG_ORD (-2139095041)

// ---------------- scratch ----------------
__device__ float    g_upe[EE*256];
__device__ float    g_Qn[NN*256];
__device__ float    g_Vn[NN*256];
__device__ float    g_Ke[EE*256];
__device__ int      g_aggI[NN*256];
__device__ float    g_agg[NN*256];
__device__ float    g_upn[NN*256];
__device__ float    g_osum[NN*256];
__device__ float    g_isum[NN*256];
__device__ int      g_ocnt[NN];
__device__ int      g_icnt[NN];
__device__ int      g_rev[EE];
__device__ unsigned g_hkey[HSZ];
__device__ int      g_hval[HSZ];
// half (fp16) buffers
__device__ __half   g_EB[EE*768];
__device__ __half   g_EC[EE*768];
__device__ __half   g_Xa[NN*768];
__device__ __half   g_Xd[NN*768];
__device__ __half   g_xr[NN*256];
__device__ __half   g_ear[EE*256];
__device__ __half   g_hbuf[EE*768];
__device__ __half   g_cat[NN*512];
__device__ __half   g_hn[NN*512];
__device__ __half   g_twin[NN*512];
__device__ __half   g_We1h[768*1024];
__device__ __half   g_We2h[256*768];
__device__ __half   g_Wqh[256*256];
__device__ __half   g_Wkh[256*256];
__device__ __half   g_Wvh[256*256];
__device__ __half   g_Wn1h[512*512];
__device__ __half   g_Wn2h[256*512];
__device__ __half   g_Weah[256*512];

__device__ __forceinline__ int f2oi(float f){
    int i = __float_as_int(f);
    return i >= 0 ? i : i ^ 0x7FFFFFFF;
}
__device__ __forceinline__ float oi2f(int i){
    return __int_as_float(i >= 0 ? i : i ^ 0x7FFFFFFF);
}

// ---------------- init ----------------
__global__ void k_init(int N){
    int i = blockIdx.x*blockDim.x + threadIdx.x;
    if(i < (int)HSZ) g_hkey[i] = 0xFFFFFFFFu;
    if(i < N*256){ g_aggI[i] = NEG_ORD; g_osum[i] = 0.f; g_isum[i] = 0.f; }
    if(i < N){ g_ocnt[i] = 0; g_icnt[i] = 0; }
}

// ---------------- fp32 -> fp16 convert pass ----------------
__global__ void k_tohalf(const float4* __restrict__ src, uint2* __restrict__ dst, int n4){
    int i = blockIdx.x*blockDim.x + threadIdx.x;
    if(i >= n4) return;
    float4 v = src[i];
    __half2 h0 = __floats2half2_rn(v.x, v.y);
    __half2 h1 = __floats2half2_rn(v.z, v.w);
    dst[i] = make_uint2(*(unsigned*)&h0, *(unsigned*)&h1);
}

// ---------------- reverse-edge hash table ----------------
__global__ void k_hash_insert(const int* __restrict__ ei, int E, int N){
    int e = blockIdx.x*blockDim.x + threadIdx.x;
    if(e >= E) return;
    unsigned key = (unsigned)ei[e] * (unsigned)N + (unsigned)ei[E+e];
    unsigned slot = ((key * 2654435761u) >> 13) & HMASK;
    while(true){
        unsigned prev = atomicCAS(&g_hkey[slot], 0xFFFFFFFFu, key);
        if(prev == 0xFFFFFFFFu){ g_hval[slot] = e; break; }
        slot = (slot + 1u) & HMASK;
    }
}

__global__ void k_rev(const int* __restrict__ ei, int E, int N){
    int e = blockIdx.x*blockDim.x + threadIdx.x;
    if(e >= E) return;
    unsigned rkey = (unsigned)ei[E+e] * (unsigned)N + (unsigned)ei[e];
    unsigned slot = ((rkey * 2654435761u) >> 13) & HMASK;
    int r = -1;
    while(true){
        unsigned kk = g_hkey[slot];
        if(kk == rkey){ r = g_hval[slot]; break; }
        if(kk == 0xFFFFFFFFu) break;
        slot = (slot + 1u) & HMASK;
    }
    g_rev[e] = r;
}

// ---- fp16 TC GEMM: 128x128 block, warp tile 64x32, cp.async 4-stage ------
#define RSH 40
#define TWB (128*RSH*2)
#define STAGES 4
#define SMEM_BYTES (STAGES*2*TWB)

__device__ __forceinline__ void mma_f16(float c[4], const unsigned a[4], const unsigned b[2]){
    asm volatile(
        "mma.sync.aligned.m16n8k16.row.col.f32.f16.f16.f32 "
        "{%0,%1,%2,%3}, {%4,%5,%6,%7}, {%8,%9}, {%0,%1,%2,%3};"
        : "+f"(c[0]), "+f"(c[1]), "+f"(c[2]), "+f"(c[3])
        : "r"(a[0]), "r"(a[1]), "r"(a[2]), "r"(a[3]), "r"(b[0]), "r"(b[1]));
}
__device__ __forceinline__ void ldsm4(unsigned &r0, unsigned &r1, unsigned &r2, unsigned &r3,
                                      unsigned addr){
    asm volatile("ldmatrix.sync.aligned.m8n8.x4.shared.b16 {%0,%1,%2,%3}, [%4];"
        : "=r"(r0), "=r"(r1), "=r"(r2), "=r"(r3) : "r"(addr));
}
__device__ __forceinline__ void cp16(unsigned daddr, const void* gptr, int srcsize){
    asm volatile("cp.async.cg.shared.global [%0], [%1], 16, %2;"
        :: "r"(daddr), "l"(gptr), "r"(srcsize));
}
__device__ __forceinline__ void cp_commit(){
    asm volatile("cp.async.commit_group;" ::: "memory");
}
__device__ __forceinline__ void cp_wait2(){
    asm volatile("cp.async.wait_group 2;" ::: "memory");
}

// modes: 0 C=v ; 1 Ch=half(relu v) ; 2 C=v & C2=relu ; 3 C=relu(aux)*sigmoid(v) ; 4 Ch=half(v)
__device__ __forceinline__ void emit(float v, size_t idx,
                                     float* C, float* C2, __half* Ch,
                                     const float* aux, int mode){
    if(mode == 0)      C[idx] = v;
    else if(mode == 1) Ch[idx] = __float2half_rn(fmaxf(v, 0.f));
    else if(mode == 2){ C[idx] = v; C2[idx] = fmaxf(v, 0.f); }
    else if(mode == 3){ float s = 1.f/(1.f + __expf(-v)); C[idx] = fmaxf(aux[idx], 0.f) * s; }
    else               Ch[idx] = __float2half_rn(v);
}

__global__ void __launch_bounds__(256, 2)
k_hgemm(int M, int Ncol, int K,
        const __half* __restrict__ A, int lda,
        const __half* __restrict__ W, int ldw,
        const float* __restrict__ bias,
        float* __restrict__ C, int ldc,
        float* __restrict__ C2, __half* __restrict__ Ch,
        const float* __restrict__ aux, int mode)
{
    extern __shared__ unsigned char smem_raw[];

    const int tid  = threadIdx.x;
    const int lane = tid & 31;
    const int warp = tid >> 5;
    const int tg   = lane & 3;
    const int g    = lane >> 2;
    const int bm   = blockIdx.y * 128;
    const int bn   = blockIdx.x * 128;
    const int mw   = (warp >> 2) * 64;
    const int nw   = (warp & 3) * 32;

    const unsigned sAaddr = (unsigned)__cvta_generic_to_shared(smem_raw);
    const unsigned sBaddr = sAaddr + STAGES*TWB;

    int cR[2], cK8[2];
    #pragma unroll
    for(int i=0;i<2;i++){
        int u = i*256 + tid;
        cR[i] = u >> 2; cK8[i] = (u & 3) << 3;
    }

    auto issue = [&](int kc, int buf){
        const int k0 = kc * 32;
        #pragma unroll
        for(int i=0;i<2;i++){
            unsigned doff = (unsigned)(buf*TWB + cR[i]*(RSH*2) + cK8[i]*2);
            int gm = bm + cR[i];
            const __half* srcA = A + (size_t)(gm < M ? gm : 0)*lda + k0 + cK8[i];
            cp16(sAaddr + doff, srcA, gm < M ? 16 : 0);
            const __half* srcB = W + (size_t)(bn + cR[i])*ldw + k0 + cK8[i];
            cp16(sBaddr + doff, srcB, 16);
        }
        cp_commit();
    };

    const int lr  = lane & 15;
    const int lc8 = (lane >> 4) << 3;
    unsigned aOff[4], bOff[2];
    #pragma unroll
    for(int mi=0;mi<4;mi++)  aOff[mi]  = (unsigned)(((mw + mi*16 + lr)*RSH + lc8) * 2);
    #pragma unroll
    for(int ni2=0;ni2<2;ni2++) bOff[ni2] = (unsigned)(((nw + ni2*16 + lr)*RSH + lc8) * 2);

    float acc[4][4][4];
    #pragma unroll
    for(int mi=0;mi<4;mi++)
        #pragma unroll
        for(int ni=0;ni<4;ni++)
            #pragma unroll
            for(int t=0;t<4;t++) acc[mi][ni][t] = 0.f;

    const int NC = K / 32;
    issue(0, 0); issue(1, 1); issue(2, 2);

    int buf = 0;
    for(int c=0; c<NC; c++){
        cp_wait2();
        __syncthreads();

        if (c + 3 < NC) issue(c + 3, (buf + 3) & 3);
        else            cp_commit();

        const unsigned aBase = sAaddr + (unsigned)(buf*TWB);
        const unsigned bBase = sBaddr + (unsigned)(buf*TWB);
        #pragma unroll
        for(int ks=0;ks<32;ks+=16){
            unsigned af[4][4], bf[4][2];
            #pragma unroll
            for(int mi=0;mi<4;mi++)
                ldsm4(af[mi][0], af[mi][1], af[mi][2], af[mi][3],
                      aBase + aOff[mi] + (unsigned)(ks*2));
            #pragma unroll
            for(int ni2=0;ni2<2;ni2++){
                unsigned r0,r1,r2,r3;
                ldsm4(r0, r1, r2, r3, bBase + bOff[ni2] + (unsigned)(ks*2));
                bf[ni2*2+0][0] = r0; bf[ni2*2+0][1] = r2;
                bf[ni2*2+1][0] = r1; bf[ni2*2+1][1] = r3;
            }
            #pragma unroll
            for(int mi=0;mi<4;mi++)
                #pragma unroll
                for(int ni=0;ni<4;ni++)
                    mma_f16(acc[mi][ni], af[mi], bf[ni]);
        }
        buf = (buf + 1) & 3;
    }

    // ---- epilogue
    #pragma unroll
    for(int mi=0;mi<4;mi++){
        int row0 = bm + mw + mi*16 + g;
        int row1 = row0 + 8;
        #pragma unroll
        for(int ni=0;ni<4;ni++){
            int col = bn + nw + ni*8 + tg*2;
            float b0 = bias ? bias[col]   : 0.f;
            float b1 = bias ? bias[col+1] : 0.f;
            if(row0 < M){
                size_t i0 = (size_t)row0*ldc + col;
                emit(acc[mi][ni][0] + b0, i0,   C, C2, Ch, aux, mode);
                emit(acc[mi][ni][1] + b1, i0+1, C, C2, Ch, aux, mode);
            }
            if(row1 < M){
                size_t i1 = (size_t)row1*ldc + col;
                emit(acc[mi][ni][2] + b0, i1,   C, C2, Ch, aux, mode);
                emit(acc[mi][ni][3] + b1, i1+1, C, C2, Ch, aux, mode);
            }
        }
    }
}

// ---------------- combine (all-fp16 buffers): h = relu(Xa[row]+EB+EC[rev]+Xd[col]+be1)
__global__ void k_combine(const int* __restrict__ ei,
                          const float* __restrict__ be1, int E){
    long long gid = (long long)blockIdx.x*blockDim.x + threadIdx.x;
    if(gid >= (long long)E*192) return;
    int e = (int)(gid/192);
    int q = (int)(gid%192);
    int j = q*4;
    int r  = ei[e], c = ei[E+e], rv = g_rev[e];

    uint2 uv  = *(const uint2*)(g_EB + (size_t)e*768 + j);
    uint2 uxa = *(const uint2*)(g_Xa + (size_t)r*768 + j);
    uint2 uxd = *(const uint2*)(g_Xd + (size_t)c*768 + j);
    float4 b  = *(const float4*)(be1 + j);

    float2 v0  = __half22float2(*(__half2*)&uv.x);
    float2 v1  = __half22float2(*(__half2*)&uv.y);
    float2 xa0 = __half22float2(*(__half2*)&uxa.x);
    float2 xa1 = __half22float2(*(__half2*)&uxa.y);
    float2 xd0 = __half22float2(*(__half2*)&uxd.x);
    float2 xd1 = __half22float2(*(__half2*)&uxd.y);

    float o0 = v0.x + xa0.x + xd0.x + b.x;
    float o1 = v0.y + xa0.y + xd0.y + b.y;
    float o2 = v1.x + xa1.x + xd1.x + b.z;
    float o3 = v1.y + xa1.y + xd1.y + b.w;
    if(rv >= 0){
        uint2 uec = *(const uint2*)(g_EC + (size_t)rv*768 + j);
        float2 e0 = __half22float2(*(__half2*)&uec.x);
        float2 e1 = __half22float2(*(__half2*)&uec.y);
        o0 += e0.x; o1 += e0.y; o2 += e1.x; o3 += e1.y;
    }
    __half2 h0 = __floats2half2_rn(fmaxf(o0,0.f), fmaxf(o1,0.f));
    __half2 h1 = __floats2half2_rn(fmaxf(o2,0.f), fmaxf(o3,0.f));
    *(uint2*)(g_hbuf + (size_t)e*768 + j) = make_uint2(*(unsigned*)&h0, *(unsigned*)&h1);
}

// ---------------- fused attention MLP + softmax + weighted + scatter-max
__global__ void __launch_bounds__(256)
k_attn(const int* __restrict__ ei,
       const float* __restrict__ Wa1, const float* __restrict__ ba1,
       const float* __restrict__ Wa2, const float* __restrict__ ba2,
       float* __restrict__ out_prob, int E)
{
    __shared__ float4 sW1[1024];
    __shared__ float4 sW2[512];
    __shared__ float  sb1[64], sb2[32];
    for(int i=threadIdx.x;i<1024;i+=256) sW1[i] = ((const float4*)Wa1)[i];
    for(int i=threadIdx.x;i<512; i+=256) sW2[i] = ((const float4*)Wa2)[i];
    if(threadIdx.x < 64) sb1[threadIdx.x] = ba1[threadIdx.x];
    if(threadIdx.x < 32) sb2[threadIdx.x] = ba2[threadIdx.x];
    __syncthreads();

    long long gid = (long long)blockIdx.x*256 + threadIdx.x;
    if(gid >= (long long)E*8) return;
    int e = (int)(gid >> 3);
    int h = (int)(gid & 7);
    int r = ei[e], c = ei[E+e];

    float ain[64];
    const float* qrow = g_Qn + (size_t)r*256 + h;
    const float* krow = g_Ke + (size_t)e*256 + h;
    #pragma unroll
    for(int i=0;i<32;i++) ain[i]    = qrow[i*8];
    #pragma unroll
    for(int i=0;i<32;i++) ain[32+i] = krow[i*8];

    float att[32];
    #pragma unroll
    for(int p=0;p<32;p++) att[p] = sb2[p];

    #pragma unroll 1
    for(int o4=0;o4<16;o4++){
        float a1v[4];
        #pragma unroll
        for(int s=0;s<4;s++){
            int o = o4*4 + s;
            float a = sb1[o];
            #pragma unroll
            for(int c4=0;c4<16;c4++){
                float4 w = sW1[o*16 + c4];
                a += w.x*ain[c4*4+0] + w.y*ain[c4*4+1]
                   + w.z*ain[c4*4+2] + w.w*ain[c4*4+3];
            }
            a1v[s] = fmaxf(a, 0.f);
        }
        #pragma unroll
        for(int p=0;p<32;p++){
            float4 w = sW2[p*16 + o4];
            att[p] += w.x*a1v[0] + w.y*a1v[1] + w.z*a1v[2] + w.w*a1v[3];
        }
    }

    const float invT = 0.17677669529663687f;
    float mx = att[0];
    #pragma unroll
    for(int p=1;p<32;p++) mx = fmaxf(mx, att[p]);
    float sum = 0.f;
    #pragma unroll
    for(int p=0;p<32;p++){ att[p] = __expf((att[p]-mx)*invT); sum += att[p]; }
    float inv = 1.f/sum;

    float* pp = out_prob + (size_t)e*256 + h;
    const float* vrow = g_Vn + (size_t)c*256 + h;
    int* ar = g_aggI + r*256 + h;
    #pragma unroll
    for(int p=0;p<32;p++){
        float pr = att[p]*inv;
        pp[p*8] = pr;
        float w = pr * vrow[p*8];
        atomicMax(ar + p*8, f2oi(w));
    }
}

// ---------------- small elementwise kernels ----------------
__global__ void k_agg_final(int N){
    int i = blockIdx.x*blockDim.x + threadIdx.x;
    if(i >= N*256) return;
    float v = oi2f(g_aggI[i]);
    g_agg[i] = isfinite(v) ? v : 0.f;
}

__global__ void k_concat(const float* __restrict__ x, int N){
    int i = blockIdx.x*blockDim.x + threadIdx.x;
    if(i >= N*512) return;
    int n = i >> 9, j = i & 511;
    float v = (j < 256) ? x[(size_t)n*256 + j] : g_agg[(size_t)n*256 + j - 256];
    g_cat[i] = __float2half_rn(v);
}

__global__ void k_counts(const int* __restrict__ ei, int E){
    int e = blockIdx.x*blockDim.x + threadIdx.x;
    if(e >= E) return;
    atomicAdd(&g_ocnt[ei[e]],   1);
    atomicAdd(&g_icnt[ei[E+e]], 1);
}

__global__ void k_twin_scatter(const int* __restrict__ ei, int E){
    long long gid = (long long)blockIdx.x*blockDim.x + threadIdx.x;
    if(gid >= (long long)E*64) return;
    int e  = (int)(gid >> 6);
    int j4 = (int)(gid & 63);
    int r = ei[e], c = ei[E+e];
    float4 u = *(const float4*)(g_upe + (size_t)e*256 + j4*4);
    int base = j4*4;
    atomicAdd(&g_osum[r*256+base+0], u.x);
    atomicAdd(&g_osum[r*256+base+1], u.y);
    atomicAdd(&g_osum[r*256+base+2], u.z);
    atomicAdd(&g_osum[r*256+base+3], u.w);
    atomicAdd(&g_isum[c*256+base+0], u.x);
    atomicAdd(&g_isum[c*256+base+1], u.y);
    atomicAdd(&g_isum[c*256+base+2], u.z);
    atomicAdd(&g_isum[c*256+base+3], u.w);
}

__global__ void k_twin_final(int N){
    int i = blockIdx.x*blockDim.x + threadIdx.x;
    if(i >= N*512) return;
    int n = i >> 9, j = i & 511;
    float v;
    if(j < 256) v = g_osum[n*256 + j]       / fmaxf((float)g_ocnt[n], 1.f);
    else        v = g_isum[n*256 + j - 256] / fmaxf((float)g_icnt[n], 1.f);
    g_twin[i] = __float2half_rn(v);
}

// ---------------- launcher ----------------
extern "C" void kernel_launch(void* const* d_in, const int* in_sizes, int n_in,
                              void* d_out, int out_size)
{
    const float* x   = (const float*)d_in[0];
    const float* ea  = (const float*)d_in[1];
    const float* Wq  = (const float*)d_in[2];
    const float* bq  = (const float*)d_in[3];
    const float* Wk  = (const float*)d_in[4];
    const float* bk  = (const float*)d_in[5];
    const float* Wv  = (const float*)d_in[6];
    const float* bv  = (const float*)d_in[7];
    const float* We1 = (const float*)d_in[8];
    const float* be1 = (const float*)d_in[9];
    const float* We2 = (const float*)d_in[10];
    const float* be2 = (const float*)d_in[11];
    const float* Wea = (const float*)d_in[12];
    const float* bea = (const float*)d_in[13];
    const float* Wn1 = (const float*)d_in[14];
    const float* bn1 = (const float*)d_in[15];
    const float* Wn2 = (const float*)d_in[16];
    const float* bn2 = (const float*)d_in[17];
    const float* Wa1 = (const float*)d_in[18];
    const float* ba1 = (const float*)d_in[19];
    const float* Wa2 = (const float*)d_in[20];
    const float* ba2 = (const float*)d_in[21];
    const int*   ei  = (const int*)  d_in[22];

    const int N = in_sizes[0]/256;
    const int E = in_sizes[1]/256;

    float* out      = (float*)d_out;
    float* out_node = out;
    float* out_edge = out + (size_t)N*256;
    float* out_prob = out_edge + (size_t)E*256;

    void* p;
    #define GSYMF(v, s) float* v; cudaGetSymbolAddress(&p, s); v = (float*)p;
    #define GSYMH(v, s) __half* v; cudaGetSymbolAddress(&p, s); v = (__half*)p;
    GSYMF(pUPE, g_upe)
    GSYMF(pQ,   g_Qn)  GSYMF(pV,   g_Vn)  GSYMF(pK,  g_Ke)
    GSYMF(pUpn, g_upn)
    GSYMH(pXa,  g_Xa)  GSYMH(pXd,  g_Xd)  GSYMH(pEB, g_EB) GSYMH(pEC, g_EC)
    GSYMH(pH,   g_hbuf)
    GSYMH(pCat, g_cat) GSYMH(pHn, g_hn)  GSYMH(pTwin, g_twin)
    GSYMH(pXr,  g_xr)  GSYMH(pEar, g_ear)
    GSYMH(pWe1h, g_We1h) GSYMH(pWe2h, g_We2h)
    GSYMH(pWqh, g_Wqh) GSYMH(pWkh, g_Wkh) GSYMH(pWvh, g_Wvh)
    GSYMH(pWn1h, g_Wn1h) GSYMH(pWn2h, g_Wn2h) GSYMH(pWeah, g_Weah)
    #undef GSYMF
    #undef GSYMH

    cudaFuncSetAttribute(k_hgemm, cudaFuncAttributeMaxDynamicSharedMemorySize, SMEM_BYTES);

    auto H = [&](const float* src, __half* dst, int n){
        k_tohalf<<<(n/4 + 255)/256, 256>>>((const float4*)src, (uint2*)dst, n/4);
    };
    H(x,   pXr,   N*256);
    H(ea,  pEar,  E*256);
    H(We1, pWe1h, 768*1024);
    H(We2, pWe2h, 256*768);
    H(Wq,  pWqh,  256*256);
    H(Wk,  pWkh,  256*256);
    H(Wv,  pWvh,  256*256);
    H(Wn1, pWn1h, 512*512);
    H(Wn2, pWn2h, 256*512);
    H(Wea, pWeah, 256*512);

    k_init<<<(NN*256+255)/256, 256>>>(N);
    k_hash_insert<<<(E+255)/256, 256>>>(ei, E, N);
    k_rev<<<(E+255)/256, 256>>>(ei, E, N);

    auto GEMM = [&](int M, int Nc, int K, const __half* A, int lda,
                    const __half* W, int ldw, const float* bias,
                    float* C, int ldc, float* C2, __half* Ch,
                    const float* aux, int mode){
        dim3 g(Nc/128, (M+127)/128);
        k_hgemm<<<g, 256, SMEM_BYTES>>>(M, Nc, K, A, lda, W, ldw, bias,
                                        C, ldc, C2, Ch, aux, mode);
    };

    // edge-update MLP, factored by We1 column blocks (half outputs, mode 4)
    GEMM(N, 768, 256, pXr,  256, pWe1h + 0,   1024, nullptr, nullptr, 768, nullptr, pXa, nullptr, 4);
    GEMM(N, 768, 256, pXr,  256, pWe1h + 768, 1024, nullptr, nullptr, 768, nullptr, pXd, nullptr, 4);
    GEMM(E, 768, 256, pEar, 256, pWe1h + 256, 1024, nullptr, nullptr, 768, nullptr, pEB, nullptr, 4);
    GEMM(E, 768, 256, pEar, 256, pWe1h + 512, 1024, nullptr, nullptr, 768, nullptr, pEC, nullptr, 4);
    k_combine<<<(int)(((long long)E*192 + 255)/256), 256>>>(ei, be1, E);
    GEMM(E, 256, 768, pH, 768, pWe2h, 768, be2, pUPE, 256, out_edge, nullptr, nullptr, 2);

    // q/v per node, k per edge
    GEMM(N, 256, 256, pXr,  256, pWqh, 256, bq, pQ, 256, nullptr, nullptr, nullptr, 0);
    GEMM(N, 256, 256, pXr,  256, pWvh, 256, bv, pV, 256, nullptr, nullptr, nullptr, 0);
    GEMM(E, 256, 256, pEar, 256, pWkh, 256, bk, pK, 256, nullptr, nullptr, nullptr, 0);

    // attention + scatter-max aggregation
    k_attn<<<(int)(((long long)E*8 + 255)/256), 256>>>(ei, Wa1, ba1, Wa2, ba2, out_prob, E);
    k_agg_final<<<(N*256+255)/256, 256>>>(N);

    // node update MLP
    k_concat<<<(N*512+255)/256, 256>>>(x, N);
    GEMM(N, 512, 512, pCat, 512, pWn1h, 512, bn1, nullptr, 512, nullptr, pHn, nullptr, 1);
    GEMM(N, 256, 512, pHn,  512, pWn2h, 512, bn2, pUpn, 256, nullptr, nullptr, nullptr, 0);

    // twin aggregation + gated output
    k_counts<<<(E+255)/256, 256>>>(ei, E);
    k_twin_scatter<<<(int)(((long long)E*64 + 255)/256), 256>>>(ei, E);
    k_twin_final<<<(N*512+255)/256, 256>>>(N);
    GEMM(N, 256, 512, pTwin, 512, pWeah, 512, bea, out_node, 256, nullptr, nullptr, pUpn, 3);
}

// round 12
// speedup vs baseline: 1.2139x; 1.2139x over previous
#include <cuda_runtime.h>
#include <cuda_fp16.h>
#include <math.h>
#include <stdint.h>

// ---------------- problem constants ----------------
#define NN 20000
#define EE 200000
#define HSZ (1u<<19)
#define HMASK (HSZ-1u)
#define NEG_ORD (-2139095041)

// ---------------- scratch ----------------
__device__ float    g_upe[EE*256];
__device__ float    g_Qn[NN*256];
__device__ float    g_Vn[NN*256];
__device__ float    g_Ke[EE*256];
__device__ int      g_aggI[NN*256];
__device__ float    g_agg[NN*256];
__device__ float    g_upn[NN*256];
__device__ float    g_osum[NN*256];
__device__ float    g_isum[NN*256];
__device__ int      g_ocnt[NN];
__device__ int      g_icnt[NN];
__device__ int      g_rev[EE];
__device__ unsigned g_hkey[HSZ];
__device__ int      g_hval[HSZ];
// half (fp16) buffers
__device__ __half   g_EB[EE*768];
__device__ __half   g_EC[EE*768];
__device__ __half   g_Xa[NN*768];
__device__ __half   g_Xd[NN*768];
__device__ __half   g_xr[NN*256];
__device__ __half   g_ear[EE*256];
__device__ __half   g_hbuf[EE*768];
__device__ __half   g_cat[NN*512];
__device__ __half   g_hn[NN*512];
__device__ __half   g_twin[NN*512];
__device__ __half   g_We1h[768*1024];
__device__ __half   g_We2h[256*768];
__device__ __half   g_Wqh[256*256];
__device__ __half   g_Wkh[256*256];
__device__ __half   g_Wvh[256*256];
__device__ __half   g_Wn1h[512*512];
__device__ __half   g_Wn2h[256*512];
__device__ __half   g_Weah[256*512];

__device__ __forceinline__ int f2oi(float f){
    int i = __float_as_int(f);
    return i >= 0 ? i : i ^ 0x7FFFFFFF;
}
__device__ __forceinline__ float oi2f(int i){
    return __int_as_float(i >= 0 ? i : i ^ 0x7FFFFFFF);
}

// ---------------- init ----------------
__global__ void k_init(int N){
    int i = blockIdx.x*blockDim.x + threadIdx.x;
    if(i < (int)HSZ) g_hkey[i] = 0xFFFFFFFFu;
    if(i < N*256){ g_aggI[i] = NEG_ORD; g_osum[i] = 0.f; g_isum[i] = 0.f; }
    if(i < N){ g_ocnt[i] = 0; g_icnt[i] = 0; }
}

// ---------------- fp32 -> fp16 convert pass ----------------
__global__ void k_tohalf(const float4* __restrict__ src, uint2* __restrict__ dst, int n4){
    int i = blockIdx.x*blockDim.x + threadIdx.x;
    if(i >= n4) return;
    float4 v = src[i];
    __half2 h0 = __floats2half2_rn(v.x, v.y);
    __half2 h1 = __floats2half2_rn(v.z, v.w);
    dst[i] = make_uint2(*(unsigned*)&h0, *(unsigned*)&h1);
}

// ---------------- reverse-edge hash table ----------------
__global__ void k_hash_insert(const int* __restrict__ ei, int E, int N){
    int e = blockIdx.x*blockDim.x + threadIdx.x;
    if(e >= E) return;
    unsigned key = (unsigned)ei[e] * (unsigned)N + (unsigned)ei[E+e];
    unsigned slot = ((key * 2654435761u) >> 13) & HMASK;
    while(true){
        unsigned prev = atomicCAS(&g_hkey[slot], 0xFFFFFFFFu, key);
        if(prev == 0xFFFFFFFFu){ g_hval[slot] = e; break; }
        slot = (slot + 1u) & HMASK;
    }
}

__global__ void k_rev(const int* __restrict__ ei, int E, int N){
    int e = blockIdx.x*blockDim.x + threadIdx.x;
    if(e >= E) return;
    unsigned rkey = (unsigned)ei[E+e] * (unsigned)N + (unsigned)ei[e];
    unsigned slot = ((rkey * 2654435761u) >> 13) & HMASK;
    int r = -1;
    while(true){
        unsigned kk = g_hkey[slot];
        if(kk == rkey){ r = g_hval[slot]; break; }
        if(kk == 0xFFFFFFFFu) break;
        slot = (slot + 1u) & HMASK;
    }
    g_rev[e] = r;
}

// ---- fp16 TC GEMM: 128x128 block, warp tile 64x32, cp.async 4-stage ------
#define RSH 40
#define TWB (128*RSH*2)
#define STAGES 4
#define SMEM_BYTES (STAGES*2*TWB)

__device__ __forceinline__ void mma_f16(float c[4], const unsigned a[4], const unsigned b[2]){
    asm volatile(
        "mma.sync.aligned.m16n8k16.row.col.f32.f16.f16.f32 "
        "{%0,%1,%2,%3}, {%4,%5,%6,%7}, {%8,%9}, {%0,%1,%2,%3};"
        : "+f"(c[0]), "+f"(c[1]), "+f"(c[2]), "+f"(c[3])
        : "r"(a[0]), "r"(a[1]), "r"(a[2]), "r"(a[3]), "r"(b[0]), "r"(b[1]));
}
__device__ __forceinline__ void ldsm4(unsigned &r0, unsigned &r1, unsigned &r2, unsigned &r3,
                                      unsigned addr){
    asm volatile("ldmatrix.sync.aligned.m8n8.x4.shared.b16 {%0,%1,%2,%3}, [%4];"
        : "=r"(r0), "=r"(r1), "=r"(r2), "=r"(r3) : "r"(addr));
}
__device__ __forceinline__ void cp16(unsigned daddr, const void* gptr, int srcsize){
    asm volatile("cp.async.cg.shared.global [%0], [%1], 16, %2;"
        :: "r"(daddr), "l"(gptr), "r"(srcsize));
}
__device__ __forceinline__ void cp_commit(){
    asm volatile("cp.async.commit_group;" ::: "memory");
}
__device__ __forceinline__ void cp_wait2(){
    asm volatile("cp.async.wait_group 2;" ::: "memory");
}

// paired emit: writes columns (col, col+1) with ONE vector store.
// modes: 0 C=v(float2) ; 1 Ch=half2(relu) ; 2 C=v & C2=relu (float2 each) ;
//        3 C=relu(aux)*sigmoid(v) (float2) ; 4 Ch=half2(v)
__device__ __forceinline__ void emit2(float v0, float v1, size_t idx,
                                      float* C, float* C2, __half* Ch,
                                      const float* aux, int mode){
    if(mode == 0){
        *(float2*)(C + idx) = make_float2(v0, v1);
    } else if(mode == 1){
        __half2 h = __floats2half2_rn(fmaxf(v0,0.f), fmaxf(v1,0.f));
        *(__half2*)(Ch + idx) = h;
    } else if(mode == 2){
        *(float2*)(C  + idx) = make_float2(v0, v1);
        *(float2*)(C2 + idx) = make_float2(fmaxf(v0,0.f), fmaxf(v1,0.f));
    } else if(mode == 3){
        float2 a = *(const float2*)(aux + idx);
        float s0 = 1.f/(1.f + __expf(-v0));
        float s1 = 1.f/(1.f + __expf(-v1));
        *(float2*)(C + idx) = make_float2(fmaxf(a.x,0.f)*s0, fmaxf(a.y,0.f)*s1);
    } else {
        __half2 h = __floats2half2_rn(v0, v1);
        *(__half2*)(Ch + idx) = h;
    }
}

__global__ void __launch_bounds__(256, 2)
k_hgemm(int M, int Ncol, int K,
        const __half* __restrict__ A, int lda,
        const __half* __restrict__ W, int ldw,
        const float* __restrict__ bias,
        float* __restrict__ C, int ldc,
        float* __restrict__ C2, __half* __restrict__ Ch,
        const float* __restrict__ aux, int mode)
{
    extern __shared__ unsigned char smem_raw[];

    const int tid  = threadIdx.x;
    const int lane = tid & 31;
    const int warp = tid >> 5;
    const int tg   = lane & 3;
    const int g    = lane >> 2;
    const int bm   = blockIdx.y * 128;
    const int bn   = blockIdx.x * 128;
    const int mw   = (warp >> 2) * 64;
    const int nw   = (warp & 3) * 32;

    const unsigned sAaddr = (unsigned)__cvta_generic_to_shared(smem_raw);
    const unsigned sBaddr = sAaddr + STAGES*TWB;

    int cR[2], cK8[2];
    #pragma unroll
    for(int i=0;i<2;i++){
        int u = i*256 + tid;
        cR[i] = u >> 2; cK8[i] = (u & 3) << 3;
    }

    auto issue = [&](int kc, int buf){
        const int k0 = kc * 32;
        #pragma unroll
        for(int i=0;i<2;i++){
            unsigned doff = (unsigned)(buf*TWB + cR[i]*(RSH*2) + cK8[i]*2);
            int gm = bm + cR[i];
            const __half* srcA = A + (size_t)(gm < M ? gm : 0)*lda + k0 + cK8[i];
            cp16(sAaddr + doff, srcA, gm < M ? 16 : 0);
            const __half* srcB = W + (size_t)(bn + cR[i])*ldw + k0 + cK8[i];
            cp16(sBaddr + doff, srcB, 16);
        }
        cp_commit();
    };

    const int lr  = lane & 15;
    const int lc8 = (lane >> 4) << 3;
    unsigned aOff[4], bOff[2];
    #pragma unroll
    for(int mi=0;mi<4;mi++)  aOff[mi]  = (unsigned)(((mw + mi*16 + lr)*RSH + lc8) * 2);
    #pragma unroll
    for(int ni2=0;ni2<2;ni2++) bOff[ni2] = (unsigned)(((nw + ni2*16 + lr)*RSH + lc8) * 2);

    float acc[4][4][4];
    #pragma unroll
    for(int mi=0;mi<4;mi++)
        #pragma unroll
        for(int ni=0;ni<4;ni++)
            #pragma unroll
            for(int t=0;t<4;t++) acc[mi][ni][t] = 0.f;

    const int NC = K / 32;
    issue(0, 0); issue(1, 1); issue(2, 2);

    int buf = 0;
    for(int c=0; c<NC; c++){
        cp_wait2();
        __syncthreads();

        if (c + 3 < NC) issue(c + 3, (buf + 3) & 3);
        else            cp_commit();

        const unsigned aBase = sAaddr + (unsigned)(buf*TWB);
        const unsigned bBase = sBaddr + (unsigned)(buf*TWB);
        #pragma unroll
        for(int ks=0;ks<32;ks+=16){
            unsigned af[4][4], bf[4][2];
            #pragma unroll
            for(int mi=0;mi<4;mi++)
                ldsm4(af[mi][0], af[mi][1], af[mi][2], af[mi][3],
                      aBase + aOff[mi] + (unsigned)(ks*2));
            #pragma unroll
            for(int ni2=0;ni2<2;ni2++){
                unsigned r0,r1,r2,r3;
                ldsm4(r0, r1, r2, r3, bBase + bOff[ni2] + (unsigned)(ks*2));
                bf[ni2*2+0][0] = r0; bf[ni2*2+0][1] = r2;
                bf[ni2*2+1][0] = r1; bf[ni2*2+1][1] = r3;
            }
            #pragma unroll
            for(int mi=0;mi<4;mi++)
                #pragma unroll
                for(int ni=0;ni<4;ni++)
                    mma_f16(acc[mi][ni], af[mi], bf[ni]);
        }
        buf = (buf + 1) & 3;
    }

    // ---- epilogue (paired vector stores)
    #pragma unroll
    for(int mi=0;mi<4;mi++){
        int row0 = bm + mw + mi*16 + g;
        int row1 = row0 + 8;
        #pragma unroll
        for(int ni=0;ni<4;ni++){
            int col = bn + nw + ni*8 + tg*2;
            float b0 = bias ? bias[col]   : 0.f;
            float b1 = bias ? bias[col+1] : 0.f;
            if(row0 < M)
                emit2(acc[mi][ni][0] + b0, acc[mi][ni][1] + b1,
                      (size_t)row0*ldc + col, C, C2, Ch, aux, mode);
            if(row1 < M)
                emit2(acc[mi][ni][2] + b0, acc[mi][ni][3] + b1,
                      (size_t)row1*ldc + col, C, C2, Ch, aux, mode);
        }
    }
}

// ---------------- combine (all-fp16 buffers): h = relu(Xa[row]+EB+EC[rev]+Xd[col]+be1)
__global__ void k_combine(const int* __restrict__ ei,
                          const float* __restrict__ be1, int E){
    long long gid = (long long)blockIdx.x*blockDim.x + threadIdx.x;
    if(gid >= (long long)E*192) return;
    int e = (int)(gid/192);
    int q = (int)(gid%192);
    int j = q*4;
    int r  = ei[e], c = ei[E+e], rv = g_rev[e];

    uint2 uv  = *(const uint2*)(g_EB + (size_t)e*768 + j);
    uint2 uxa = *(const uint2*)(g_Xa + (size_t)r*768 + j);
    uint2 uxd = *(const uint2*)(g_Xd + (size_t)c*768 + j);
    float4 b  = *(const float4*)(be1 + j);

    float2 v0  = __half22float2(*(__half2*)&uv.x);
    float2 v1  = __half22float2(*(__half2*)&uv.y);
    float2 xa0 = __half22float2(*(__half2*)&uxa.x);
    float2 xa1 = __half22float2(*(__half2*)&uxa.y);
    float2 xd0 = __half22float2(*(__half2*)&uxd.x);
    float2 xd1 = __half22float2(*(__half2*)&uxd.y);

    float o0 = v0.x + xa0.x + xd0.x + b.x;
    float o1 = v0.y + xa0.y + xd0.y + b.y;
    float o2 = v1.x + xa1.x + xd1.x + b.z;
    float o3 = v1.y + xa1.y + xd1.y + b.w;
    if(rv >= 0){
        uint2 uec = *(const uint2*)(g_EC + (size_t)rv*768 + j);
        float2 e0 = __half22float2(*(__half2*)&uec.x);
        float2 e1 = __half22float2(*(__half2*)&uec.y);
        o0 += e0.x; o1 += e0.y; o2 += e1.x; o3 += e1.y;
    }
    __half2 h0 = __floats2half2_rn(fmaxf(o0,0.f), fmaxf(o1,0.f));
    __half2 h1 = __floats2half2_rn(fmaxf(o2,0.f), fmaxf(o3,0.f));
    *(uint2*)(g_hbuf + (size_t)e*768 + j) = make_uint2(*(unsigned*)&h0, *(unsigned*)&h1);
}

// ---------------- fused attention MLP + softmax + weighted + scatter-max
__global__ void __launch_bounds__(256)
k_attn(const int* __restrict__ ei,
       const float* __restrict__ Wa1, const float* __restrict__ ba1,
       const float* __restrict__ Wa2, const float* __restrict__ ba2,
       float* __restrict__ out_prob, int E)
{
    __shared__ float4 sW1[1024];
    __shared__ float4 sW2[512];
    __shared__ float  sb1[64], sb2[32];
    for(int i=threadIdx.x;i<1024;i+=256) sW1[i] = ((const float4*)Wa1)[i];
    for(int i=threadIdx.x;i<512; i+=256) sW2[i] = ((const float4*)Wa2)[i];
    if(threadIdx.x < 64) sb1[threadIdx.x] = ba1[threadIdx.x];
    if(threadIdx.x < 32) sb2[threadIdx.x] = ba2[threadIdx.x];
    __syncthreads();

    long long gid = (long long)blockIdx.x*256 + threadIdx.x;
    if(gid >= (long long)E*8) return;
    int e = (int)(gid >> 3);
    int h = (int)(gid & 7);
    int r = ei[e], c = ei[E+e];

    float ain[64];
    const float* qrow = g_Qn + (size_t)r*256 + h;
    const float* krow = g_Ke + (size_t)e*256 + h;
    #pragma unroll
    for(int i=0;i<32;i++) ain[i]    = qrow[i*8];
    #pragma unroll
    for(int i=0;i<32;i++) ain[32+i] = krow[i*8];

    float att[32];
    #pragma unroll
    for(int p=0;p<32;p++) att[p] = sb2[p];

    #pragma unroll 1
    for(int o4=0;o4<16;o4++){
        float a1v[4];
        #pragma unroll
        for(int s=0;s<4;s++){
            int o = o4*4 + s;
            float a = sb1[o];
            #pragma unroll
            for(int c4=0;c4<16;c4++){
                float4 w = sW1[o*16 + c4];
                a += w.x*ain[c4*4+0] + w.y*ain[c4*4+1]
                   + w.z*ain[c4*4+2] + w.w*ain[c4*4+3];
            }
            a1v[s] = fmaxf(a, 0.f);
        }
        #pragma unroll
        for(int p=0;p<32;p++){
            float4 w = sW2[p*16 + o4];
            att[p] += w.x*a1v[0] + w.y*a1v[1] + w.z*a1v[2] + w.w*a1v[3];
        }
    }

    const float invT = 0.17677669529663687f;
    float mx = att[0];
    #pragma unroll
    for(int p=1;p<32;p++) mx = fmaxf(mx, att[p]);
    float sum = 0.f;
    #pragma unroll
    for(int p=0;p<32;p++){ att[p] = __expf((att[p]-mx)*invT); sum += att[p]; }
    float inv = 1.f/sum;

    float* pp = out_prob + (size_t)e*256 + h;
    const float* vrow = g_Vn + (size_t)c*256 + h;
    int* ar = g_aggI + r*256 + h;
    #pragma unroll
    for(int p=0;p<32;p++){
        float pr = att[p]*inv;
        pp[p*8] = pr;
        float w = pr * vrow[p*8];
        atomicMax(ar + p*8, f2oi(w));
    }
}

// ---------------- small elementwise kernels ----------------
__global__ void k_agg_final(int N){
    int i = blockIdx.x*blockDim.x + threadIdx.x;
    if(i >= N*256) return;
    float v = oi2f(g_aggI[i]);
    g_agg[i] = isfinite(v) ? v : 0.f;
}

__global__ void k_concat(const float* __restrict__ x, int N){
    int i = blockIdx.x*blockDim.x + threadIdx.x;
    if(i >= N*512) return;
    int n = i >> 9, j = i & 511;
    float v = (j < 256) ? x[(size_t)n*256 + j] : g_agg[(size_t)n*256 + j - 256];
    g_cat[i] = __float2half_rn(v);
}

__global__ void k_counts(const int* __restrict__ ei, int E){
    int e = blockIdx.x*blockDim.x + threadIdx.x;
    if(e >= E) return;
    atomicAdd(&g_ocnt[ei[e]],   1);
    atomicAdd(&g_icnt[ei[E+e]], 1);
}

__global__ void k_twin_scatter(const int* __restrict__ ei, int E){
    long long gid = (long long)blockIdx.x*blockDim.x + threadIdx.x;
    if(gid >= (long long)E*64) return;
    int e  = (int)(gid >> 6);
    int j4 = (int)(gid & 63);
    int r = ei[e], c = ei[E+e];
    float4 u = *(const float4*)(g_upe + (size_t)e*256 + j4*4);
    int base = j4*4;
    atomicAdd(&g_osum[r*256+base+0], u.x);
    atomicAdd(&g_osum[r*256+base+1], u.y);
    atomicAdd(&g_osum[r*256+base+2], u.z);
    atomicAdd(&g_osum[r*256+base+3], u.w);
    atomicAdd(&g_isum[c*256+base+0], u.x);
    atomicAdd(&g_isum[c*256+base+1], u.y);
    atomicAdd(&g_isum[c*256+base+2], u.z);
    atomicAdd(&g_isum[c*256+base+3], u.w);
}

__global__ void k_twin_final(int N){
    int i = blockIdx.x*blockDim.x + threadIdx.x;
    if(i >= N*512) return;
    int n = i >> 9, j = i & 511;
    float v;
    if(j < 256) v = g_osum[n*256 + j]       / fmaxf((float)g_ocnt[n], 1.f);
    else        v = g_isum[n*256 + j - 256] / fmaxf((float)g_icnt[n], 1.f);
    g_twin[i] = __float2half_rn(v);
}

// ---------------- launcher ----------------
extern "C" void kernel_launch(void* const* d_in, const int* in_sizes, int n_in,
                              void* d_out, int out_size)
{
    const float* x   = (const float*)d_in[0];
    const float* ea  = (const float*)d_in[1];
    const float* Wq  = (const float*)d_in[2];
    const float* bq  = (const float*)d_in[3];
    const float* Wk  = (const float*)d_in[4];
    const float* bk  = (const float*)d_in[5];
    const float* Wv  = (const float*)d_in[6];
    const float* bv  = (const float*)d_in[7];
    const float* We1 = (const float*)d_in[8];
    const float* be1 = (const float*)d_in[9];
    const float* We2 = (const float*)d_in[10];
    const float* be2 = (const float*)d_in[11];
    const float* Wea = (const float*)d_in[12];
    const float* bea = (const float*)d_in[13];
    const float* Wn1 = (const float*)d_in[14];
    const float* bn1 = (const float*)d_in[15];
    const float* Wn2 = (const float*)d_in[16];
    const float* bn2 = (const float*)d_in[17];
    const float* Wa1 = (const float*)d_in[18];
    const float* ba1 = (const float*)d_in[19];
    const float* Wa2 = (const float*)d_in[20];
    const float* ba2 = (const float*)d_in[21];
    const int*   ei  = (const int*)  d_in[22];

    const int N = in_sizes[0]/256;
    const int E = in_sizes[1]/256;

    float* out      = (float*)d_out;
    float* out_node = out;
    float* out_edge = out + (size_t)N*256;
    float* out_prob = out_edge + (size_t)E*256;

    void* p;
    #define GSYMF(v, s) float* v; cudaGetSymbolAddress(&p, s); v = (float*)p;
    #define GSYMH(v, s) __half* v; cudaGetSymbolAddress(&p, s); v = (__half*)p;
    GSYMF(pUPE, g_upe)
    GSYMF(pQ,   g_Qn)  GSYMF(pV,   g_Vn)  GSYMF(pK,  g_Ke)
    GSYMF(pUpn, g_upn)
    GSYMH(pXa,  g_Xa)  GSYMH(pXd,  g_Xd)  GSYMH(pEB, g_EB) GSYMH(pEC, g_EC)
    GSYMH(pH,   g_hbuf)
    GSYMH(pCat, g_cat) GSYMH(pHn, g_hn)  GSYMH(pTwin, g_twin)
    GSYMH(pXr,  g_xr)  GSYMH(pEar, g_ear)
    GSYMH(pWe1h, g_We1h) GSYMH(pWe2h, g_We2h)
    GSYMH(pWqh, g_Wqh) GSYMH(pWkh, g_Wkh) GSYMH(pWvh, g_Wvh)
    GSYMH(pWn1h, g_Wn1h) GSYMH(pWn2h, g_Wn2h) GSYMH(pWeah, g_Weah)
    #undef GSYMF
    #undef GSYMH

    cudaFuncSetAttribute(k_hgemm, cudaFuncAttributeMaxDynamicSharedMemorySize, SMEM_BYTES);

    auto H = [&](const float* src, __half* dst, int n){
        k_tohalf<<<(n/4 + 255)/256, 256>>>((const float4*)src, (uint2*)dst, n/4);
    };
    H(x,   pXr,   N*256);
    H(ea,  pEar,  E*256);
    H(We1, pWe1h, 768*1024);
    H(We2, pWe2h, 256*768);
    H(Wq,  pWqh,  256*256);
    H(Wk,  pWkh,  256*256);
    H(Wv,  pWvh,  256*256);
    H(Wn1, pWn1h, 512*512);
    H(Wn2, pWn2h, 256*512);
    H(Wea, pWeah, 256*512);

    k_init<<<(NN*256+255)/256, 256>>>(N);
    k_hash_insert<<<(E+255)/256, 256>>>(ei, E, N);
    k_rev<<<(E+255)/256, 256>>>(ei, E, N);

    auto GEMM = [&](int M, int Nc, int K, const __half* A, int lda,
                    const __half* W, int ldw, const float* bias,
                    float* C, int ldc, float* C2, __half* Ch,
                    const float* aux, int mode){
        dim3 g(Nc/128, (M+127)/128);
        k_hgemm<<<g, 256, SMEM_BYTES>>>(M, Nc, K, A, lda, W, ldw, bias,
                                        C, ldc, C2, Ch, aux, mode);
    };

    // edge-update MLP, factored by We1 column blocks (half outputs, mode 4)
    GEMM(N, 768, 256, pXr,  256, pWe1h + 0,   1024, nullptr, nullptr, 768, nullptr, pXa, nullptr, 4);
    GEMM(N, 768, 256, pXr,  256, pWe1h + 768, 1024, nullptr, nullptr, 768, nullptr, pXd, nullptr, 4);
    GEMM(E, 768, 256, pEar, 256, pWe1h + 256, 1024, nullptr, nullptr, 768, nullptr, pEB, nullptr, 4);
    GEMM(E, 768, 256, pEar, 256, pWe1h + 512, 1024, nullptr, nullptr, 768, nullptr, pEC, nullptr, 4);
    k_combine<<<(int)(((long long)E*192 + 255)/256), 256>>>(ei, be1, E);
    GEMM(E, 256, 768, pH, 768, pWe2h, 768, be2, pUPE, 256, out_edge, nullptr, nullptr, 2);

    // q/v per node, k per edge
    GEMM(N, 256, 256, pXr,  256, pWqh, 256, bq, pQ, 256, nullptr, nullptr, nullptr, 0);
    GEMM(N, 256, 256, pXr,  256, pWvh, 256, bv, pV, 256, nullptr, nullptr, nullptr, 0);
    GEMM(E, 256, 256, pEar, 256, pWkh, 256, bk, pK, 256, nullptr, nullptr, nullptr, 0);

    // attention + scatter-max aggregation
    k_attn<<<(int)(((long long)E*8 + 255)/256), 256>>>(ei, Wa1, ba1, Wa2, ba2, out_prob, E);
    k_agg_final<<<(N*256+255)/256, 256>>>(N);

    // node update MLP
    k_concat<<<(N*512+255)/256, 256>>>(x, N);
    GEMM(N, 512, 512, pCat, 512, pWn1h, 512, bn1, nullptr, 512, nullptr, pHn, nullptr, 1);
    GEMM(N, 256, 512, pHn,  512, pWn2h, 512, bn2, pUpn, 256, nullptr, nullptr, nullptr, 0);

    // twin aggregation + gated output
    k_counts<<<(E+255)/256, 256>>>(ei, E);
    k_twin_scatter<<<(int)(((long long)E*64 + 255)/256), 256>>>(ei, E);
    k_twin_final<<<(N*512+255)/256, 256>>>(N);
    GEMM(N, 256, 512, pTwin, 512, pWeah, 512, bea, out_node, 256, nullptr, nullptr, pUpn, 3);
}